// round 17
// baseline (speedup 1.0000x reference)
#include <cuda_runtime.h>

#define F 1024
#define KDIM 4096            // 4 * F
#define SPLITK 16
#define KCHUNK 256           // KDIM / SPLITK
#define NTILES 16            // KCHUNK / 16

#define GEMM_BLOCKS 128      // (N/128=8) x SPLITK=16, M=128 full per block
#define N_SRC_MEM1 511
#define N_SRC_MEM2 508
#define N_SRC_INP  512
#define FAN 2                // dest-fanout split per source row
#define SCATTER_BASE GEMM_BLOCKS                                        // 128
#define NONCOMP_BLOCKS ((N_SRC_MEM1 + N_SRC_MEM2 + N_SRC_INP) * FAN)    // 3062
#define COMP_BASE (SCATTER_BASE + NONCOMP_BLOCKS)                       // 3190
#define COMP_BLOCKS (128 * FAN)                                         // 256
#define TOTAL_BLOCKS (COMP_BASE + COMP_BLOCKS)                          // 3446

// Scratch (no cudaMalloc allowed)
__device__ float g_part[SPLITK][128][F];     // 8 MB split-K partials
__device__ unsigned g_flag;                  // GEMM done counter

typedef unsigned long long u64;

// smem: 48KB. A tile (fp32, transposed) 16KB at sh[0..4095];
// B tile DUPLICATED as (b,b) u64 pairs, 32KB at sh[4096..] (viewed as u64*).
// Scatter blocks reuse sh[0..1023] as 4KB staging.
#define AS(buf,k,m)  sh[(buf)*2048 + (k)*128 + (m)]
#define BSD(buf,k,c) bsd[(buf)*2048 + (k)*128 + (c)]

__device__ __forceinline__ u64 dup2(float x) {
    unsigned u = __float_as_uint(x);
    return ((u64)u << 32) | u;
}

// Packed dual fp32 FMA (Blackwell FFMA2; only reachable via PTX fma.rn.f32x2).
__device__ __forceinline__ void ffma2(u64& d, u64 a, u64 b) {
    asm("fma.rn.f32x2 %0, %1, %2, %3;" : "=l"(d) : "l"(a), "l"(b), "l"(d));
}

// One 4KB bulk store: smem row -> global row (TMA path, single instruction).
__device__ __forceinline__ void bulk_store_row(const float* gdst, unsigned saddr) {
    asm volatile("cp.async.bulk.global.shared::cta.bulk_group [%0], [%1], %2;"
                 :: "l"(gdst), "r"(saddr), "r"(4096) : "memory");
}

// ---------------------------------------------------------------------------
// One fused kernel.
//   blocks [0,128)       : split-K fp32 GEMM part[kz]=X[128,4096]@W[4096,1024]
//                          128x128 tile, BK=16, 8x8 microtile computed as
//                          4 rowpairs x 8 cols of packed fma.rn.f32x2 (FFMA2)
//                          -> half the FMA-pipe work of scalar FFMA, bit-exact
//                          fp32. Double-buffered smem + register prefetch.
//   blocks [128,3190)    : non-comp scatter (stage 4KB row, TMA bulk stores).
//   blocks [3190,3446)   : comp rows (tail): wait flag, combine 16 split-K
//                          partials + bias, stage, bulk-store.
// Wait cannot deadlock: GEMM blocks occupy the lowest indices -> wave 1.
// Scatter map (inversion of the gather; each source row read ONCE):
//   memory[r], r=1..511   -> (b, r-b-1)       for b = 0..min(r-1,127)
//   memory[516+d], d<508  -> (b, 512+d-4b)    for b = 0..(d>>2) [<=126]
//   inputs[j],  j=0..511  -> (b, 1020-4b+j)   for b = (j>>2)..127
//   comp[c],    c=0..127  -> (b, 511-b+c)     for b = c..127
// ---------------------------------------------------------------------------
__global__ __launch_bounds__(256) void OSAR_fused(
    const float* __restrict__ inputs, const float* __restrict__ memory,
    const float* __restrict__ W, const float* __restrict__ bias,
    float* __restrict__ out)
{
    __shared__ float sh[12288];                       // 48KB
    u64* bsd = (u64*)(sh + 4096);                     // duplicated B tiles

    const int bid = blockIdx.x;
    const int tid = threadIdx.x;

    // ================= GEMM blocks =================
    if (bid < GEMM_BLOCKS) {
        const int kz = bid & 15;          // K chunk
        const int bn = bid >> 4;          // 0..7 (N tile of 128)

        const float* Xb = memory + 512 * F + kz * KCHUNK;
        const float* Wb = W + (size_t)(kz * KCHUNK) * F + bn * 128;

        // A load: 2 float4/thread; idx=tid*2+i -> row=idx>>2 (0..127), slot=idx&3
        // B load: 2 float4/thread; idx=tid*2+i -> krow=idx>>5 (0..15), ns=idx&31
        const int ty = tid >> 4, tx = tid & 15;   // 16x16 grid, 8x8 microtile

        u64 acc[4][8];                    // [rowpair][col], packed fp32 pairs
#pragma unroll
        for (int p = 0; p < 4; p++)
#pragma unroll
            for (int c = 0; c < 8; c++) acc[p][c] = 0ull;

        float4 av[2], bv[2];
#pragma unroll
        for (int i = 0; i < 2; i++) {
            int idx = tid * 2 + i;
            av[i] = *(const float4*)(Xb + (size_t)(idx >> 2) * KDIM + (idx & 3) * 4);
            bv[i] = *(const float4*)(Wb + (size_t)(idx >> 5) * F + (idx & 31) * 4);
        }
#pragma unroll
        for (int i = 0; i < 2; i++) {
            int idx = tid * 2 + i;
            int row = idx >> 2, slot = idx & 3;
            AS(0, slot * 4 + 0, row) = av[i].x;
            AS(0, slot * 4 + 1, row) = av[i].y;
            AS(0, slot * 4 + 2, row) = av[i].z;
            AS(0, slot * 4 + 3, row) = av[i].w;
            int kr = idx >> 5, nc = (idx & 31) * 4;
            BSD(0, kr, nc + 0) = dup2(bv[i].x);
            BSD(0, kr, nc + 1) = dup2(bv[i].y);
            BSD(0, kr, nc + 2) = dup2(bv[i].z);
            BSD(0, kr, nc + 3) = dup2(bv[i].w);
        }
        __syncthreads();

        int cur = 0;
        for (int t = 0; t < NTILES; t++) {
            if (t + 1 < NTILES) {   // prefetch next tile into registers
#pragma unroll
                for (int i = 0; i < 2; i++) {
                    int idx = tid * 2 + i;
                    av[i] = *(const float4*)(Xb + (size_t)(idx >> 2) * KDIM +
                                             (t + 1) * 16 + (idx & 3) * 4);
                    bv[i] = *(const float4*)(Wb + (size_t)((t + 1) * 16 + (idx >> 5)) * F +
                                             (idx & 31) * 4);
                }
            }
#pragma unroll
            for (int k = 0; k < 16; k++) {
                u64 areg[4];
#pragma unroll
                for (int p = 0; p < 4; p++)   // rowpair (2p, 2p+1): one LDS.64
                    areg[p] = *(const u64*)&AS(cur, k, ty * 8 + 2 * p);
                u64 breg[8];
#pragma unroll
                for (int c2 = 0; c2 < 4; c2++) {  // two dup'd cols: one LDS.128
                    ulonglong2 t2 = *(const ulonglong2*)&BSD(cur, k, tx * 8 + 2 * c2);
                    breg[2 * c2] = t2.x; breg[2 * c2 + 1] = t2.y;
                }
#pragma unroll
                for (int p = 0; p < 4; p++)
#pragma unroll
                    for (int c = 0; c < 8; c++)
                        ffma2(acc[p][c], areg[p], breg[c]);
            }
            if (t + 1 < NTILES) {
                int nxt = cur ^ 1;
#pragma unroll
                for (int i = 0; i < 2; i++) {
                    int idx = tid * 2 + i;
                    int row = idx >> 2, slot = idx & 3;
                    AS(nxt, slot * 4 + 0, row) = av[i].x;
                    AS(nxt, slot * 4 + 1, row) = av[i].y;
                    AS(nxt, slot * 4 + 2, row) = av[i].z;
                    AS(nxt, slot * 4 + 3, row) = av[i].w;
                    int kr = idx >> 5, nc = (idx & 31) * 4;
                    BSD(nxt, kr, nc + 0) = dup2(bv[i].x);
                    BSD(nxt, kr, nc + 1) = dup2(bv[i].y);
                    BSD(nxt, kr, nc + 2) = dup2(bv[i].z);
                    BSD(nxt, kr, nc + 3) = dup2(bv[i].w);
                }
            }
            __syncthreads();
            cur ^= 1;
        }

        // unpack: acc[p][c] = (row 2p : lo, row 2p+1 : hi) at col c
        float* dst = &g_part[kz][ty * 8][bn * 128 + tx * 8];
#pragma unroll
        for (int p = 0; p < 4; p++) {
            float r0[8], r1[8];
#pragma unroll
            for (int c = 0; c < 8; c++) {
                r0[c] = __uint_as_float((unsigned)acc[p][c]);
                r1[c] = __uint_as_float((unsigned)(acc[p][c] >> 32));
            }
            float* d0 = dst + (size_t)(2 * p) * F;
            float* d1 = dst + (size_t)(2 * p + 1) * F;
            *(float4*)d0       = make_float4(r0[0], r0[1], r0[2], r0[3]);
            *(float4*)(d0 + 4) = make_float4(r0[4], r0[5], r0[6], r0[7]);
            *(float4*)d1       = make_float4(r1[0], r1[1], r1[2], r1[3]);
            *(float4*)(d1 + 4) = make_float4(r1[4], r1[5], r1[6], r1[7]);
        }

        __syncthreads();
        if (tid == 0) { __threadfence(); atomicAdd(&g_flag, 1u); }
        return;
    }

    const int lane = tid & 31;
    const int wid  = tid >> 5;
    const unsigned saddr = (unsigned)__cvta_generic_to_shared(sh);

    // ================= non-comp scatter blocks =================
    if (bid < COMP_BASE) {
        const int cid = bid - SCATTER_BASE;
        const int sid = cid >> 1;          // source row id
        const int y   = cid & 1;           // fanout half

        int mode, p0, cnt;                 // dest row = f(mode, p0, b)
        const float* src;
        if (sid < N_SRC_MEM1) {
            const int r = sid + 1;                         // memory row 1..511
            src = memory + (size_t)r * F;
            mode = 0; p0 = r; cnt = min(r, 128);
        } else if (sid < N_SRC_MEM1 + N_SRC_MEM2) {
            const int d = sid - N_SRC_MEM1;                // 0..507
            src = memory + (size_t)(516 + d) * F;
            mode = 1; p0 = d; cnt = min(d >> 2, 126) + 1;
        } else {
            const int j = sid - (N_SRC_MEM1 + N_SRC_MEM2); // 0..511
            src = inputs + (size_t)j * F;
            mode = 2; p0 = j; cnt = 128;
        }

        ((float4*)sh)[tid] = ((const float4*)src)[tid];    // stage 4KB
        __syncthreads();

        if (lane == 0) {
            asm volatile("fence.proxy.async.shared::cta;" ::: "memory");
            const int b0 = (mode == 2) ? ((p0 >> 2) + y) : y;
            for (int b = b0 + wid * FAN; b < cnt; b += 8 * FAN) {
                int m;
                if (mode == 0)      m = p0 - b - 1;
                else if (mode == 1) m = 512 + p0 - 4 * b;
                else                m = 1020 - 4 * b + p0;
                bulk_store_row(out + ((size_t)b * 1024 + m) * F, saddr);
            }
            asm volatile("cp.async.bulk.commit_group;" ::: "memory");
            asm volatile("cp.async.bulk.wait_group 0;" ::: "memory");
        }
        return;
    }

    // ================= comp scatter blocks (grid tail) =================
    {
        const int cid = bid - COMP_BASE;
        const int c = cid >> 1;            // comp row 0..127
        const int y = cid & 1;

        if (tid == 0) {
            volatile unsigned* f = &g_flag;
            while (*f < GEMM_BLOCKS) __nanosleep(128);
            __threadfence();
        }
        __syncthreads();

        float4 v = ((const float4*)bias)[tid];
#pragma unroll
        for (int z = 0; z < SPLITK; z++) {
            float4 p = ((const float4*)g_part[z][c])[tid];
            v.x += p.x; v.y += p.y; v.z += p.z; v.w += p.w;
        }
        ((float4*)sh)[tid] = v;            // stage combined comp row
        __syncthreads();

        if (lane == 0) {
            asm volatile("fence.proxy.async.shared::cta;" ::: "memory");
            for (int b = c + y + wid * FAN; b < 128; b += 8 * FAN)
                bulk_store_row(out + ((size_t)b * 1024 + 511 - b + c) * F, saddr);
            asm volatile("cp.async.bulk.commit_group;" ::: "memory");
            asm volatile("cp.async.bulk.wait_group 0;" ::: "memory");
        }
    }
}

// ---------------------------------------------------------------------------
extern "C" void kernel_launch(void* const* d_in, const int* in_sizes, int n_in,
                              void* d_out, int out_size) {
    const float* inputs = (const float*)d_in[0];   // (128, 4, 1024)
    const float* memory = (const float*)d_in[1];   // (1024, 1024)
    const float* kern   = (const float*)d_in[2];   // (4, 1024, 1024)
    const float* bias   = (const float*)d_in[3];   // (1024,)
    float* out = (float*)d_out;                    // (128, 1024, 1024)

    void* flagAddr = nullptr;
    cudaGetSymbolAddress(&flagAddr, g_flag);
    cudaMemsetAsync(flagAddr, 0, sizeof(unsigned));

    OSAR_fused<<<TOTAL_BLOCKS, 256>>>(inputs, memory, kern, bias, out);
}